// round 1
// baseline (speedup 1.0000x reference)
#include <cuda_runtime.h>
#include <cuda_bf16.h>
#include <math.h>

#define B_ 2
#define T_ 2048
#define C_ 2048
#define NH_ 16
#define NKV_ 8
#define HD_ 128
#define M_ (B_*T_)            // 4096 rows
#define QKVC_ ((NH_+2*NKV_)*HD_)  // 4096

// Scratch (device globals: allocation-free per harness rules)
__device__ float g_qkv[(size_t)M_ * QKVC_];   // 64 MB
__device__ float g_att[(size_t)M_ * C_];      // 32 MB

// ---------------------------------------------------------------------------
// SGEMM: C[M,N] = A[M,K] * B[K,N], row-major. M,N multiples of 128, K of 8.
// 128x128 block tile, BK=8, 256 threads, 8x8 per thread.
// ---------------------------------------------------------------------------
__global__ __launch_bounds__(256, 2)
void sgemm128(const float* __restrict__ A, const float* __restrict__ Bm,
              float* __restrict__ Cm, int Md, int Nd, int Kd)
{
    __shared__ float As[8][128];   // transposed A tile: As[k][m]
    __shared__ float Bs[8][128];   // Bs[k][n]

    const int tid = threadIdx.x;
    const int tx = tid & 15;
    const int ty = tid >> 4;
    const int aRow = tid >> 1;
    const int aCol = (tid & 1) << 2;
    const int bRow = tid >> 5;
    const int bCol = (tid & 31) << 2;

    const float* Ap = A + (size_t)(blockIdx.y * 128 + aRow) * Kd + aCol;
    const float* Bp = Bm + (size_t)bRow * Nd + blockIdx.x * 128 + bCol;

    float acc[8][8];
    #pragma unroll
    for (int i = 0; i < 8; i++)
        #pragma unroll
        for (int j = 0; j < 8; j++) acc[i][j] = 0.f;

    for (int k0 = 0; k0 < Kd; k0 += 8) {
        float4 av = *(const float4*)Ap;
        float4 bv = *(const float4*)Bp;
        Ap += 8;
        Bp += (size_t)8 * Nd;
        As[aCol + 0][aRow] = av.x;
        As[aCol + 1][aRow] = av.y;
        As[aCol + 2][aRow] = av.z;
        As[aCol + 3][aRow] = av.w;
        *(float4*)&Bs[bRow][bCol] = bv;
        __syncthreads();

        #pragma unroll
        for (int k = 0; k < 8; k++) {
            float ar[8], br[8];
            float4 t;
            t = *(const float4*)&As[k][ty * 4];      ar[0]=t.x; ar[1]=t.y; ar[2]=t.z; ar[3]=t.w;
            t = *(const float4*)&As[k][64 + ty * 4]; ar[4]=t.x; ar[5]=t.y; ar[6]=t.z; ar[7]=t.w;
            t = *(const float4*)&Bs[k][tx * 4];      br[0]=t.x; br[1]=t.y; br[2]=t.z; br[3]=t.w;
            t = *(const float4*)&Bs[k][64 + tx * 4]; br[4]=t.x; br[5]=t.y; br[6]=t.z; br[7]=t.w;
            #pragma unroll
            for (int i = 0; i < 8; i++)
                #pragma unroll
                for (int j = 0; j < 8; j++)
                    acc[i][j] = fmaf(ar[i], br[j], acc[i][j]);
        }
        __syncthreads();
    }

    #pragma unroll
    for (int i = 0; i < 8; i++) {
        int m = blockIdx.y * 128 + ((i < 4) ? (ty * 4 + i) : (64 + ty * 4 + i - 4));
        float* cp = Cm + (size_t)m * Nd + blockIdx.x * 128;
        *(float4*)(cp + tx * 4)      = make_float4(acc[i][0], acc[i][1], acc[i][2], acc[i][3]);
        *(float4*)(cp + 64 + tx * 4) = make_float4(acc[i][4], acc[i][5], acc[i][6], acc[i][7]);
    }
}

// ---------------------------------------------------------------------------
// RoPE (in place on g_qkv, q heads 0..15 and k heads 16..23).
// ---------------------------------------------------------------------------
__global__ void rope_kernel(const float* __restrict__ cosb, const float* __restrict__ sinb)
{
    int idx = blockIdx.x * blockDim.x + threadIdx.x;
    const int total = M_ * (NH_ + NKV_) * (HD_ / 2);
    if (idx >= total) return;
    int pair = idx & 63;
    int tmp  = idx >> 6;
    int head = tmp % (NH_ + NKV_);
    int row  = tmp / (NH_ + NKV_);
    int t = row & (T_ - 1);
    float c = cosb[t * 64 + pair];
    float s = sinb[t * 64 + pair];
    float* p = g_qkv + (size_t)row * QKVC_ + head * HD_ + pair * 2;
    float2 v = *(float2*)p;
    float2 r;
    r.x = fmaf(v.x, c, -v.y * s);
    r.y = fmaf(v.x, s,  v.y * c);
    *(float2*)p = r;
}

// ---------------------------------------------------------------------------
// Flash attention (causal, GQA). One block per (qtile of 64 rows, b*NH head).
// smem: Qs[64][128], Ks[64][132], Vs[64][132], Ps[64][65]  (116992 B dynamic)
// ---------------------------------------------------------------------------
#define SMO_K (64 * 128)
#define SMO_V (SMO_K + 64 * 132)
#define SMO_P (SMO_V + 64 * 132)
#define SM_TOT_BYTES ((SMO_P + 64 * 65) * 4)

__global__ __launch_bounds__(256, 1)
void attn_kernel()
{
    extern __shared__ float sm[];
    float* Qs = sm;
    float* Ks = sm + SMO_K;
    float* Vs = sm + SMO_V;
    float* Ps = sm + SMO_P;

    const int qt = blockIdx.x;          // 0..31
    const int bh = blockIdx.y;          // 0..31
    const int b  = bh >> 4;
    const int h  = bh & 15;
    const int kvh = h >> 1;             // GQA group
    const int tid = threadIdx.x;
    const int tx = tid & 15;
    const int ty = tid >> 4;
    const int rowbase = b * T_ + qt * 64;
    const float scale = 0.088388347648318447f;  // 1/sqrt(128)

    // Load Q tile
    {
        const float* src = g_qkv + (size_t)rowbase * QKVC_ + h * HD_;
        #pragma unroll
        for (int it = 0; it < 8; it++) {
            int idx = it * 256 + tid;
            int r  = idx >> 5;
            int c4 = (idx & 31) << 2;
            *(float4*)(Qs + r * 128 + c4) = *(const float4*)(src + (size_t)r * QKVC_ + c4);
        }
    }

    float o[4][8];
    float m_i[4], l_i[4];
    #pragma unroll
    for (int r = 0; r < 4; r++) {
        m_i[r] = -1e30f; l_i[r] = 0.f;
        #pragma unroll
        for (int c = 0; c < 8; c++) o[r][c] = 0.f;
    }

    const int kv_end = (qt + 1) * 64;
    for (int kv0 = 0; kv0 < kv_end; kv0 += 64) {
        const float* ksrc = g_qkv + (size_t)(b * T_ + kv0) * QKVC_ + NH_ * HD_ + kvh * HD_;
        const float* vsrc = ksrc + NKV_ * HD_;
        __syncthreads();   // previous PV reads of Vs/Ps done (also orders Q load)
        #pragma unroll
        for (int it = 0; it < 8; it++) {
            int idx = it * 256 + tid;
            int r  = idx >> 5;
            int c4 = (idx & 31) << 2;
            *(float4*)(Ks + r * 132 + c4) = *(const float4*)(ksrc + (size_t)r * QKVC_ + c4);
            *(float4*)(Vs + r * 132 + c4) = *(const float4*)(vsrc + (size_t)r * QKVC_ + c4);
        }
        __syncthreads();

        // S = Q K^T  : thread rows i = 4*ty+r, cols j = tx + 16*c
        float s4[4][4];
        #pragma unroll
        for (int r = 0; r < 4; r++)
            #pragma unroll
            for (int c = 0; c < 4; c++) s4[r][c] = 0.f;

        for (int d = 0; d < 128; d += 4) {
            float4 aq[4], bq[4];
            #pragma unroll
            for (int r = 0; r < 4; r++)
                aq[r] = *(const float4*)(Qs + (4 * ty + r) * 128 + d);
            #pragma unroll
            for (int c = 0; c < 4; c++)
                bq[c] = *(const float4*)(Ks + (tx + 16 * c) * 132 + d);
            #pragma unroll
            for (int r = 0; r < 4; r++)
                #pragma unroll
                for (int c = 0; c < 4; c++) {
                    s4[r][c] = fmaf(aq[r].x, bq[c].x, s4[r][c]);
                    s4[r][c] = fmaf(aq[r].y, bq[c].y, s4[r][c]);
                    s4[r][c] = fmaf(aq[r].z, bq[c].z, s4[r][c]);
                    s4[r][c] = fmaf(aq[r].w, bq[c].w, s4[r][c]);
                }
        }

        // online softmax (only the diagonal tile needs masking)
        const bool diag = (kv0 == qt * 64);
        #pragma unroll
        for (int r = 0; r < 4; r++) {
            int i = qt * 64 + 4 * ty + r;
            float mx = -1e30f;
            #pragma unroll
            for (int c = 0; c < 4; c++) {
                float v = s4[r][c] * scale;
                if (diag && (kv0 + tx + 16 * c) > i) v = -1e30f;
                s4[r][c] = v;
                mx = fmaxf(mx, v);
            }
            #pragma unroll
            for (int off = 8; off > 0; off >>= 1)
                mx = fmaxf(mx, __shfl_xor_sync(0xffffffffu, mx, off));
            float mnew = fmaxf(m_i[r], mx);
            float alpha = __expf(m_i[r] - mnew);
            m_i[r] = mnew;
            float rs = 0.f;
            float p4[4];
            #pragma unroll
            for (int c = 0; c < 4; c++) {
                float p = __expf(s4[r][c] - mnew);
                p4[c] = p;
                rs += p;
            }
            #pragma unroll
            for (int off = 8; off > 0; off >>= 1)
                rs += __shfl_xor_sync(0xffffffffu, rs, off);
            l_i[r] = l_i[r] * alpha + rs;
            #pragma unroll
            for (int c = 0; c < 8; c++) o[r][c] *= alpha;
            #pragma unroll
            for (int c = 0; c < 4; c++)
                Ps[(4 * ty + r) * 65 + tx + 16 * c] = p4[c];
        }
        __syncthreads();

        // O += P V : thread rows i = 4*ty+r, cols d = tx + 16*c
        #pragma unroll 4
        for (int j = 0; j < 64; j++) {
            float a_[4], bv[8];
            #pragma unroll
            for (int r = 0; r < 4; r++) a_[r] = Ps[(4 * ty + r) * 65 + j];
            #pragma unroll
            for (int c = 0; c < 8; c++) bv[c] = Vs[j * 132 + tx + 16 * c];
            #pragma unroll
            for (int r = 0; r < 4; r++)
                #pragma unroll
                for (int c = 0; c < 8; c++)
                    o[r][c] = fmaf(a_[r], bv[c], o[r][c]);
        }
    }

    // epilogue
    #pragma unroll
    for (int r = 0; r < 4; r++) {
        float inv = 1.f / l_i[r];
        float* dst = g_att + (size_t)(rowbase + 4 * ty + r) * C_ + h * HD_;
        #pragma unroll
        for (int c = 0; c < 8; c++)
            dst[tx + 16 * c] = o[r][c] * inv;
    }
}

// ---------------------------------------------------------------------------
extern "C" void kernel_launch(void* const* d_in, const int* in_sizes, int n_in,
                              void* d_out, int out_size)
{
    const float* x      = (const float*)d_in[0];
    const float* w_attn = (const float*)d_in[1];
    const float* w_proj = (const float*)d_in[2];
    const float* fcos   = (const float*)d_in[3];
    const float* fsin   = (const float*)d_in[4];
    float* out = (float*)d_out;

    float *qkv_ptr = nullptr, *att_ptr = nullptr;
    cudaGetSymbolAddress((void**)&qkv_ptr, g_qkv);
    cudaGetSymbolAddress((void**)&att_ptr, g_att);
    cudaFuncSetAttribute(attn_kernel, cudaFuncAttributeMaxDynamicSharedMemorySize, SM_TOT_BYTES);

    // 1) qkv = x @ w_attn   (M=4096, N=4096, K=2048)
    sgemm128<<<dim3(QKVC_ / 128, M_ / 128), 256>>>(x, w_attn, qkv_ptr, M_, QKVC_, C_);

    // 2) RoPE on q (16 heads) + k (8 heads), in place
    {
        int total = M_ * (NH_ + NKV_) * (HD_ / 2);
        rope_kernel<<<(total + 255) / 256, 256>>>(fcos, fsin);
    }

    // 3) causal GQA flash attention -> g_att (B,T,C layout)
    attn_kernel<<<dim3(T_ / 64, B_ * NH_), 256, SM_TOT_BYTES>>>();

    // 4) out = att @ w_proj (M=4096, N=2048, K=2048)
    sgemm128<<<dim3(C_ / 128, M_ / 128), 256>>>(att_ptr, w_proj, out, M_, C_, C_);
}

// round 3
// speedup vs baseline: 5.8574x; 5.8574x over previous
#include <cuda_runtime.h>
#include <cuda_fp16.h>
#include <cstdint>
#include <math.h>

#define B_ 2
#define T_ 2048
#define C_ 2048
#define NH_ 16
#define NKV_ 8
#define HD_ 128
#define M_ (B_*T_)               // 4096
#define QKVC_ 4096
#define QSCALE 0.088388347648318447f  // 1/sqrt(128)

// Scratch (device globals; allocation-free per harness rules)
__device__ float  g_qkv [(size_t)M_ * QKVC_];   // fp32 qkv (GEMM1 out)
__device__ __half g_hx  [(size_t)M_ * C_];      // fp16 x
__device__ __half g_hwa [(size_t)C_ * QKVC_];   // fp16 w_attn
__device__ __half g_hwp [(size_t)C_ * C_];      // fp16 w_proj
__device__ __half g_hqkv[(size_t)M_ * QKVC_];   // fp16 qkv post-rope (q pre-scaled)
__device__ __half g_hatt[(size_t)M_ * C_];      // fp16 attention out

// ---------------------------------------------------------------------------
// PTX helpers
// ---------------------------------------------------------------------------
__device__ __forceinline__ void cpa16(uint32_t s, const void* g) {
    asm volatile("cp.async.cg.shared.global [%0], [%1], 16;\n" :: "r"(s), "l"(g));
}
__device__ __forceinline__ void cp_commit() { asm volatile("cp.async.commit_group;\n"); }
__device__ __forceinline__ void cp_wait0()  { asm volatile("cp.async.wait_group 0;\n"); }
__device__ __forceinline__ void cp_wait1()  { asm volatile("cp.async.wait_group 1;\n"); }

__device__ __forceinline__ void ldsm4(uint32_t* r, uint32_t addr) {
    asm volatile("ldmatrix.sync.aligned.m8n8.x4.shared.b16 {%0,%1,%2,%3},[%4];\n"
                 : "=r"(r[0]), "=r"(r[1]), "=r"(r[2]), "=r"(r[3]) : "r"(addr));
}
__device__ __forceinline__ void ldsm4t(uint32_t* r, uint32_t addr) {
    asm volatile("ldmatrix.sync.aligned.m8n8.x4.trans.shared.b16 {%0,%1,%2,%3},[%4];\n"
                 : "=r"(r[0]), "=r"(r[1]), "=r"(r[2]), "=r"(r[3]) : "r"(addr));
}
__device__ __forceinline__ void mma16816(float* c, const uint32_t* a, uint32_t b0, uint32_t b1) {
    asm volatile("mma.sync.aligned.m16n8k16.row.col.f32.f16.f16.f32 "
                 "{%0,%1,%2,%3},{%4,%5,%6,%7},{%8,%9},{%0,%1,%2,%3};\n"
                 : "+f"(c[0]), "+f"(c[1]), "+f"(c[2]), "+f"(c[3])
                 : "r"(a[0]), "r"(a[1]), "r"(a[2]), "r"(a[3]), "r"(b0), "r"(b1));
}

// ---------------------------------------------------------------------------
// fp32 -> fp16 conversion
// ---------------------------------------------------------------------------
__global__ void f2h(const float4* __restrict__ s, __half2* __restrict__ d, int n4) {
    int i = blockIdx.x * blockDim.x + threadIdx.x;
    if (i >= n4) return;
    float4 v = s[i];
    d[2 * i]     = __floats2half2_rn(v.x, v.y);
    d[2 * i + 1] = __floats2half2_rn(v.z, v.w);
}

// ---------------------------------------------------------------------------
// RoPE + convert: g_qkv (fp32) -> g_hqkv (fp16). q heads scaled by 1/sqrt(HD).
// ---------------------------------------------------------------------------
__global__ void rope_cvt(const float* __restrict__ cosb, const float* __restrict__ sinb) {
    int idx = blockIdx.x * blockDim.x + threadIdx.x;       // one half2 pair
    if (idx >= M_ * (QKVC_ / 2)) return;
    int p   = idx & 2047;         // pair index within row
    int row = idx >> 11;
    int head = p >> 6;
    int pr = p & 63;
    float2 v = *(const float2*)(g_qkv + (size_t)row * QKVC_ + p * 2);
    float2 r = v;
    if (head < 24) {
        int t = row & (T_ - 1);
        float c = cosb[t * 64 + pr];
        float s = sinb[t * 64 + pr];
        r.x = v.x * c - v.y * s;
        r.y = v.x * s + v.y * c;
        if (head < 16) { r.x *= QSCALE; r.y *= QSCALE; }
    }
    ((__half2*)(g_hqkv + (size_t)row * QKVC_))[p] = __floats2half2_rn(r.x, r.y);
}

// ---------------------------------------------------------------------------
// fp16 GEMM: C[M,N](fp32) = A[M,K](fp16) * B[K,N](fp16)
// 128x128 block, BK=32, cp.async double buffer, 8 warps, warp tile 64x32.
// ---------------------------------------------------------------------------
#define A_STRIDE 40    // halves per A smem row (32 + 8 pad -> 80B)
#define B_STRIDE 136   // halves per B smem row (128 + 8 pad -> 272B)
#define A_BUF (128 * A_STRIDE)
#define B_BUF (32 * B_STRIDE)

__device__ __forceinline__ void gemm_load_tiles(
    const __half* __restrict__ A, const __half* __restrict__ Bm,
    uint32_t sA, uint32_t sB, int tid, int bm, int bn, int Nd, int Kd,
    int buf, int k0)
{
    #pragma unroll
    for (int i = 0; i < 2; i++) {
        int id = tid + i * 256;
        int r = id >> 2, cc = id & 3;
        cpa16(sA + (uint32_t)(buf * A_BUF + r * A_STRIDE + cc * 8) * 2,
              A + (size_t)(bm + r) * Kd + k0 + cc * 8);
    }
    #pragma unroll
    for (int i = 0; i < 2; i++) {
        int id = tid + i * 256;
        int r = id >> 4, cc = id & 15;
        cpa16(sB + (uint32_t)(buf * B_BUF + r * B_STRIDE + cc * 8) * 2,
              Bm + (size_t)(k0 + r) * Nd + bn + cc * 8);
    }
    cp_commit();
}

__global__ __launch_bounds__(256)
void hgemm(const __half* __restrict__ A, const __half* __restrict__ Bm,
           float* __restrict__ Cm, int Nd, int Kd)
{
    __shared__ __half As[2 * A_BUF];
    __shared__ __half Bs[2 * B_BUF];

    const int tid = threadIdx.x;
    const int lane = tid & 31, wid = tid >> 5;
    const int wm = (wid >> 2) * 64, wn = (wid & 3) * 32;
    const int bm = blockIdx.y * 128, bn = blockIdx.x * 128;
    const uint32_t sA = (uint32_t)__cvta_generic_to_shared(As);
    const uint32_t sB = (uint32_t)__cvta_generic_to_shared(Bs);

    float acc[4][4][4];
    #pragma unroll
    for (int i = 0; i < 4; i++)
        #pragma unroll
        for (int j = 0; j < 4; j++)
            #pragma unroll
            for (int k = 0; k < 4; k++) acc[i][j][k] = 0.f;

    const int KT = Kd >> 5;
    gemm_load_tiles(A, Bm, sA, sB, tid, bm, bn, Nd, Kd, 0, 0);

    for (int kt = 0; kt < KT; kt++) {
        int buf = kt & 1;
        if (kt + 1 < KT) {
            gemm_load_tiles(A, Bm, sA, sB, tid, bm, bn, Nd, Kd, buf ^ 1, (kt + 1) * 32);
            cp_wait1();
        } else {
            cp_wait0();
        }
        __syncthreads();

        #pragma unroll
        for (int ks = 0; ks < 32; ks += 16) {
            uint32_t af[4][4];
            #pragma unroll
            for (int mi = 0; mi < 4; mi++) {
                uint32_t addr = sA + (uint32_t)(buf * A_BUF +
                    (wm + mi * 16 + (lane & 15)) * A_STRIDE + ks + (lane >> 4) * 8) * 2;
                ldsm4(af[mi], addr);
            }
            uint32_t bf[4][2];
            #pragma unroll
            for (int nh = 0; nh < 2; nh++) {
                int row = ks + ((lane >> 3) & 1) * 8 + (lane & 7);
                int col = wn + nh * 16 + (lane >> 4) * 8;
                uint32_t r[4];
                ldsm4t(r, sB + (uint32_t)(buf * B_BUF + row * B_STRIDE + col) * 2);
                bf[nh * 2][0] = r[0]; bf[nh * 2][1] = r[1];
                bf[nh * 2 + 1][0] = r[2]; bf[nh * 2 + 1][1] = r[3];
            }
            #pragma unroll
            for (int mi = 0; mi < 4; mi++)
                #pragma unroll
                for (int ni = 0; ni < 4; ni++)
                    mma16816(acc[mi][ni], af[mi], bf[ni][0], bf[ni][1]);
        }
        __syncthreads();
    }

    const int g = lane >> 2, t4 = lane & 3;
    #pragma unroll
    for (int mi = 0; mi < 4; mi++)
        #pragma unroll
        for (int ni = 0; ni < 4; ni++) {
            int gr = bm + wm + mi * 16 + g;
            int gc = bn + wn + ni * 8 + t4 * 2;
            *(float2*)(Cm + (size_t)gr * Nd + gc) = make_float2(acc[mi][ni][0], acc[mi][ni][1]);
            *(float2*)(Cm + (size_t)(gr + 8) * Nd + gc) = make_float2(acc[mi][ni][2], acc[mi][ni][3]);
        }
}

// ---------------------------------------------------------------------------
// FlashAttention-2, fp16 mma. 128 Q rows/CTA, KV tiles of 64, 8 warps (m16 each).
// Q pre-scaled by 1/sqrt(HD) in rope_cvt. S-frags reused as P A-frags.
// ---------------------------------------------------------------------------
#define QK_STRIDE 136
#define SM_Q (128 * QK_STRIDE)
#define SM_K (64 * QK_STRIDE)
#define ATTN_SMEM ((SM_Q + 2 * SM_K) * 2)   // bytes = 69632

__global__ __launch_bounds__(256)
void attn_mma()
{
    extern __shared__ __half sh[];
    __half* Qs = sh;
    __half* Ks = sh + SM_Q;
    __half* Vs = sh + SM_Q + SM_K;
    const uint32_t sQ = (uint32_t)__cvta_generic_to_shared(Qs);
    const uint32_t sK = (uint32_t)__cvta_generic_to_shared(Ks);
    const uint32_t sV = (uint32_t)__cvta_generic_to_shared(Vs);

    const int tid = threadIdx.x;
    const int lane = tid & 31, wid = tid >> 5;
    const int g = lane >> 2, t4 = lane & 3;
    const int qt = blockIdx.x;           // 0..15
    const int bh = blockIdx.y;           // 0..31
    const int b = bh >> 4, h = bh & 15;
    const int kvh = h >> 1;
    const int rowbase = b * T_ + qt * 128;

    // async-load Q tile (128 x 128 halves)
    {
        const __half* qsrc = g_hqkv + (size_t)rowbase * QKVC_ + h * HD_;
        #pragma unroll
        for (int i = 0; i < 8; i++) {
            int id = tid + i * 256;
            int r = id >> 4, cc = id & 15;
            cpa16(sQ + (uint32_t)(r * QK_STRIDE + cc * 8) * 2,
                  qsrc + (size_t)r * QKVC_ + cc * 8);
        }
        cp_commit();
    }

    float of[16][4];
    #pragma unroll
    for (int i = 0; i < 16; i++)
        #pragma unroll
        for (int j = 0; j < 4; j++) of[i][j] = 0.f;
    float m0 = -1e30f, m1 = -1e30f, l0 = 0.f, l1 = 0.f;

    const int nkv = 2 * (qt + 1);
    const int rg = qt * 128 + wid * 16 + g;   // global q row for c0/c1; +8 for c2/c3

    for (int it = 0; it < nkv; it++) {
        const int kv0 = it * 64;
        __syncthreads();   // previous tile's reads complete
        {
            const __half* ksrc = g_hqkv + (size_t)(b * T_ + kv0) * QKVC_ + NH_ * HD_ + kvh * HD_;
            const __half* vsrc = ksrc + NKV_ * HD_;
            #pragma unroll
            for (int i = 0; i < 4; i++) {
                int id = tid + i * 256;
                int r = id >> 4, cc = id & 15;
                cpa16(sK + (uint32_t)(r * QK_STRIDE + cc * 8) * 2, ksrc + (size_t)r * QKVC_ + cc * 8);
            }
            #pragma unroll
            for (int i = 0; i < 4; i++) {
                int id = tid + i * 256;
                int r = id >> 4, cc = id & 15;
                cpa16(sV + (uint32_t)(r * QK_STRIDE + cc * 8) * 2, vsrc + (size_t)r * QKVC_ + cc * 8);
            }
            cp_commit();
            cp_wait0();
            __syncthreads();
        }

        // S = Q K^T (S pre-scaled since Q is scaled)
        float sf[8][4];
        #pragma unroll
        for (int i = 0; i < 8; i++)
            #pragma unroll
            for (int j = 0; j < 4; j++) sf[i][j] = 0.f;

        #pragma unroll
        for (int ks = 0; ks < 128; ks += 16) {
            uint32_t aq[4];
            ldsm4(aq, sQ + (uint32_t)((wid * 16 + (lane & 15)) * QK_STRIDE + ks + (lane >> 4) * 8) * 2);
            #pragma unroll
            for (int nq = 0; nq < 4; nq++) {
                uint32_t r[4];
                ldsm4(r, sK + (uint32_t)((nq * 16 + (lane & 15)) * QK_STRIDE + ks + (lane >> 4) * 8) * 2);
                mma16816(sf[nq * 2],     aq, r[0], r[2]);
                mma16816(sf[nq * 2 + 1], aq, r[1], r[3]);
            }
        }

        // causal mask (only tiles overlapping the diagonal can clip)
        if (kv0 + 64 > qt * 128) {
            #pragma unroll
            for (int j = 0; j < 8; j++) {
                int col = kv0 + j * 8 + t4 * 2;
                if (col     > rg)     sf[j][0] = -1e30f;
                if (col + 1 > rg)     sf[j][1] = -1e30f;
                if (col     > rg + 8) sf[j][2] = -1e30f;
                if (col + 1 > rg + 8) sf[j][3] = -1e30f;
            }
        }

        // online softmax
        float mx0 = -1e30f, mx1 = -1e30f;
        #pragma unroll
        for (int j = 0; j < 8; j++) {
            mx0 = fmaxf(mx0, fmaxf(sf[j][0], sf[j][1]));
            mx1 = fmaxf(mx1, fmaxf(sf[j][2], sf[j][3]));
        }
        #pragma unroll
        for (int off = 1; off <= 2; off <<= 1) {
            mx0 = fmaxf(mx0, __shfl_xor_sync(0xffffffffu, mx0, off));
            mx1 = fmaxf(mx1, __shfl_xor_sync(0xffffffffu, mx1, off));
        }
        float mn0 = fmaxf(m0, mx0), mn1 = fmaxf(m1, mx1);
        float al0 = __expf(m0 - mn0), al1 = __expf(m1 - mn1);
        m0 = mn0; m1 = mn1;
        float rs0 = 0.f, rs1 = 0.f;
        #pragma unroll
        for (int j = 0; j < 8; j++) {
            sf[j][0] = __expf(sf[j][0] - mn0);
            sf[j][1] = __expf(sf[j][1] - mn0);
            sf[j][2] = __expf(sf[j][2] - mn1);
            sf[j][3] = __expf(sf[j][3] - mn1);
            rs0 += sf[j][0] + sf[j][1];
            rs1 += sf[j][2] + sf[j][3];
        }
        #pragma unroll
        for (int off = 1; off <= 2; off <<= 1) {
            rs0 += __shfl_xor_sync(0xffffffffu, rs0, off);
            rs1 += __shfl_xor_sync(0xffffffffu, rs1, off);
        }
        l0 = l0 * al0 + rs0;
        l1 = l1 * al1 + rs1;
        #pragma unroll
        for (int nf = 0; nf < 16; nf++) {
            of[nf][0] *= al0; of[nf][1] *= al0;
            of[nf][2] *= al1; of[nf][3] *= al1;
        }

        // O += P V  (P from sf regs)
        #pragma unroll
        for (int kc = 0; kc < 4; kc++) {
            uint32_t pa[4];
            __half2 hh0 = __floats2half2_rn(sf[2 * kc][0],     sf[2 * kc][1]);
            __half2 hh1 = __floats2half2_rn(sf[2 * kc][2],     sf[2 * kc][3]);
            __half2 hh2 = __floats2half2_rn(sf[2 * kc + 1][0], sf[2 * kc + 1][1]);
            __half2 hh3 = __floats2half2_rn(sf[2 * kc + 1][2], sf[2 * kc + 1][3]);
            pa[0] = *(uint32_t*)&hh0; pa[1] = *(uint32_t*)&hh1;
            pa[2] = *(uint32_t*)&hh2; pa[3] = *(uint32_t*)&hh3;
            #pragma unroll
            for (int nq = 0; nq < 8; nq++) {
                int row = kc * 16 + ((lane >> 3) & 1) * 8 + (lane & 7);
                int col = nq * 16 + (lane >> 4) * 8;
                uint32_t r[4];
                ldsm4t(r, sV + (uint32_t)(row * QK_STRIDE + col) * 2);
                mma16816(of[nq * 2],     pa, r[0], r[1]);
                mma16816(of[nq * 2 + 1], pa, r[2], r[3]);
            }
        }
    }

    // epilogue
    float inv0 = 1.f / l0, inv1 = 1.f / l1;
    __half* dst = g_hatt + (size_t)(rowbase + wid * 16 + g) * C_ + h * HD_;
    #pragma unroll
    for (int nf = 0; nf < 16; nf++) {
        int col = nf * 8 + t4 * 2;
        *(__half2*)(dst + col) = __floats2half2_rn(of[nf][0] * inv0, of[nf][1] * inv0);
        *(__half2*)(dst + (size_t)8 * C_ + col) = __floats2half2_rn(of[nf][2] * inv1, of[nf][3] * inv1);
    }
}

// ---------------------------------------------------------------------------
extern "C" void kernel_launch(void* const* d_in, const int* in_sizes, int n_in,
                              void* d_out, int out_size)
{
    const float* x      = (const float*)d_in[0];
    const float* w_attn = (const float*)d_in[1];
    const float* w_proj = (const float*)d_in[2];
    const float* fcos   = (const float*)d_in[3];
    const float* fsin   = (const float*)d_in[4];
    float* out = (float*)d_out;

    float* qkv_ptr = 0;
    __half* hx = 0; __half* hwa = 0; __half* hwp = 0; __half* hqkv = 0; __half* hatt = 0;
    cudaGetSymbolAddress((void**)&qkv_ptr, g_qkv);
    cudaGetSymbolAddress((void**)&hx, g_hx);
    cudaGetSymbolAddress((void**)&hwa, g_hwa);
    cudaGetSymbolAddress((void**)&hwp, g_hwp);
    cudaGetSymbolAddress((void**)&hqkv, g_hqkv);
    cudaGetSymbolAddress((void**)&hatt, g_hatt);
    cudaFuncSetAttribute(attn_mma, cudaFuncAttributeMaxDynamicSharedMemorySize, ATTN_SMEM);

    // 0) fp32 -> fp16 conversions
    int n4a = M_ * C_ / 4;
    f2h<<<(n4a + 255) / 256, 256>>>((const float4*)x, (__half2*)hx, n4a);
    int n4b = C_ * QKVC_ / 4;
    f2h<<<(n4b + 255) / 256, 256>>>((const float4*)w_attn, (__half2*)hwa, n4b);
    int n4c = C_ * C_ / 4;
    f2h<<<(n4c + 255) / 256, 256>>>((const float4*)w_proj, (__half2*)hwp, n4c);

    // 1) qkv = x @ w_attn (M=4096, N=4096, K=2048), fp32 out
    hgemm<<<dim3(QKVC_ / 128, M_ / 128), 256>>>(hx, hwa, qkv_ptr, QKVC_, C_);

    // 2) RoPE + convert to fp16 (q pre-scaled by 1/sqrt(HD))
    int totalr = M_ * (QKVC_ / 2);
    rope_cvt<<<(totalr + 255) / 256, 256>>>(fcos, fsin);

    // 3) causal GQA flash attention (fp16 mma) -> g_hatt
    attn_mma<<<dim3(T_ / 128, B_ * NH_), 256, ATTN_SMEM>>>();

    // 4) out = att @ w_proj (M=4096, N=2048, K=2048), fp32 out
    hgemm<<<dim3(C_ / 128, M_ / 128), 256>>>(hatt, hwp, out, C_, C_);
}